// round 3
// baseline (speedup 1.0000x reference)
#include <cuda_runtime.h>
#include <math.h>

#define B_ 32
#define NN 131072
#define NEG 0.2f

// ---------------- scratch (device globals; zero-initialized, no allocation) ----
__device__ __align__(16) float g_qs[B_ * 512 * 3];   // shifted query points
__device__ __align__(16) float g_q1[B_ * 256 * 3];   // stage-1 selected points
__device__ __align__(16) float g_q2[B_ * 128 * 3];   // stage-2 selected points
__device__ __align__(16) float g_x[136 * NN];        // channel-major GEMM input
__device__ __align__(16) float g_gate[NN];           // sigmoid(dist)
__device__ __align__(16) float g_ya[128 * NN];       // conv-a output
__device__ __align__(16) float g_yb[256 * NN];       // conv-b output
__device__ __align__(16) float g_f1[B_ * 128 * 256]; // stage-1 features (B,C,M)
__device__ float2 g_stats[256];                      // per-channel (sum, sumsq)

// ---------------- packed f32x2 helpers ----------------
__device__ __forceinline__ unsigned long long pk2(float a) {
    unsigned long long r;
    asm("mov.b64 %0, {%1, %1};" : "=l"(r) : "f"(a));
    return r;
}
__device__ __forceinline__ unsigned long long f2fma(unsigned long long a,
                                                    unsigned long long b,
                                                    unsigned long long c) {
    unsigned long long d;
    asm("fma.rn.f32x2 %0, %1, %2, %3;" : "=l"(d) : "l"(a), "l"(b), "l"(c));
    return d;
}

// ---------------- shift_point ----------------
__global__ void shift_kernel(const float* __restrict__ xyz, float* __restrict__ q, int N) {
    int i = blockIdx.x * blockDim.x + threadIdx.x;
    if (i >= B_ * N) return;
    int b = i / N, n = i - b * N;
    int l = b & 15;
    if (l < 15) {
        const float* s = xyz + ((size_t)(b + 1) * N + n) * 3;
        float* d = q + (size_t)i * 3;
        d[0] = s[0]; d[1] = s[1]; d[2] = s[2];
    } else {
        int b0 = b - 15;
        #pragma unroll
        for (int c = 0; c < 3; c++) {
            float s = 0.f;
            for (int t = 0; t < 15; t++)
                s = __fadd_rn(s, __fsub_rn(xyz[((size_t)(b0 + t + 1) * N + n) * 3 + c],
                                           xyz[((size_t)(b0 + t) * N + n) * 3 + c]));
            q[(size_t)i * 3 + c] = __fadd_rn(xyz[((size_t)b * N + n) * 3 + c],
                                             __fdiv_rn(s, 15.f));
        }
    }
}

// ---------------- farthest point sampling (one block of N threads per batch) ----
__global__ void fps_kernel(const float* __restrict__ q, float* __restrict__ qsel,
                           int N, int NP) {
    __shared__ float sx[512], sy[512], sz[512];
    __shared__ unsigned long long wkey[16];
    int b = blockIdx.x, tid = threadIdx.x;
    const float* qb = q + (size_t)b * N * 3;
    float px = qb[tid * 3 + 0], py = qb[tid * 3 + 1], pz = qb[tid * 3 + 2];
    sx[tid] = px; sy[tid] = py; sz[tid] = pz;
    float mind = 1e10f;
    __syncthreads();
    float lx = sx[0], ly = sy[0], lz = sz[0];
    if (tid == 0) {
        float* d = qsel + (size_t)b * NP * 3;
        d[0] = lx; d[1] = ly; d[2] = lz;
    }
    int nw = N >> 5;
    for (int t = 1; t < NP; t++) {
        float dx = __fsub_rn(px, lx), dy = __fsub_rn(py, ly), dz = __fsub_rn(pz, lz);
        float d = __fadd_rn(__fadd_rn(__fmul_rn(dx, dx), __fmul_rn(dy, dy)),
                            __fmul_rn(dz, dz));
        mind = fminf(mind, d);
        // argmax with first-index tiebreak: pack (bits(mind) << 32) | (N-1-idx)
        unsigned long long key = (((unsigned long long)__float_as_uint(mind)) << 32)
                               | (unsigned)(N - 1 - tid);
        #pragma unroll
        for (int off = 16; off; off >>= 1) {
            unsigned long long o = __shfl_xor_sync(0xffffffffu, key, off);
            if (o > key) key = o;
        }
        if ((tid & 31) == 0) wkey[tid >> 5] = key;
        __syncthreads();
        unsigned long long best = wkey[0];
        for (int w = 1; w < nw; w++) { unsigned long long o = wkey[w]; if (o > best) best = o; }
        int bi = N - 1 - (int)(best & 0xffffffffu);
        lx = sx[bi]; ly = sy[bi]; lz = sz[bi];
        if (tid == 0) {
            float* d2 = qsel + ((size_t)b * NP + t) * 3;
            d2[0] = lx; d2[1] = ly; d2[2] = lz;
        }
        __syncthreads();   // protect wkey reuse
    }
}

// ---------------- ball query + build GEMM input + gate (one warp per query) ----
__global__ void group_kernel(const float* __restrict__ q, int M,
                             const float* __restrict__ sup, int N,
                             const float* __restrict__ feats, int C, int feat_xyz,
                             float r2, float radius, int K,
                             float* __restrict__ x, float* __restrict__ gate) {
    int gw = (blockIdx.x * blockDim.x + threadIdx.x) >> 5;
    int lane = threadIdx.x & 31;
    int wl = threadIdx.x >> 5;
    __shared__ int slist[8][32];
    if (gw >= B_ * M) return;
    int b = gw / M, m = gw - b * M;
    const float* qp = q + ((size_t)b * M + m) * 3;
    float qx = qp[0], qy = qp[1], qz = qp[2];
    const float* xb = sup + (size_t)b * N * 3;
    int count = 0;
    for (int base = 0; base < N; base += 32) {
        int j = base + lane;
        float dx = __fsub_rn(qx, xb[j * 3 + 0]);
        float dy = __fsub_rn(qy, xb[j * 3 + 1]);
        float dz = __fsub_rn(qz, xb[j * 3 + 2]);
        float d2 = __fadd_rn(__fadd_rn(__fmul_rn(dx, dx), __fmul_rn(dy, dy)),
                             __fmul_rn(dz, dz));
        bool in = d2 < r2;
        unsigned bal = __ballot_sync(0xffffffffu, in);
        int pos = count + __popc(bal & ((1u << lane) - 1u));
        if (in && pos < K) slist[wl][pos] = j;
        count += __popc(bal);
        if (count >= K) break;
    }
    if (count > K) count = K;
    __syncwarp();
    int pad = (count > 0) ? slist[wl][0] : 0;
    if (lane < K && lane >= count) slist[wl][lane] = pad;
    __syncwarp();
    int nb = ((int)b * M + m) * K;
    if (lane < K) {
        int j = slist[wl][lane];
        float gx = xb[j * 3 + 0], gy = xb[j * 3 + 1], gz = xb[j * 3 + 2];
        float dpx = (gx - qx) / radius, dpy = (gy - qy) / radius, dpz = (gz - qz) / radius;
        x[0 * NN + nb + lane] = dpx;
        x[1 * NN + nb + lane] = dpy;
        x[2 * NN + nb + lane] = dpz;
        float dist = sqrtf(dpx * dpx + dpy * dpy + dpz * dpz);
        gate[nb + lane] = 1.0f / (1.0f + expf(-dist));
        if (feat_xyz) {
            x[3 * NN + nb + lane] = gx;
            x[4 * NN + nb + lane] = gy;
            x[5 * NN + nb + lane] = gz;
        } else {
            for (int c = 0; c < C; c++)
                x[(size_t)(3 + c) * NN + nb + lane] = feats[((size_t)b * C + c) * N + j];
        }
    }
}

// ---------------- GEMM: Y[o][NN] = W[o][c] * X[c][NN] (f32x2 inner) ------------
// 64(o) x 128(n) tile, 256 threads, each thread 4(o) x 4(f32x2 pairs of n)
__global__ void __launch_bounds__(256) gemm_kernel(
    const float* __restrict__ W, const float* __restrict__ X,
    float* __restrict__ Y, int C, int Cp) {
    __shared__ __align__(16) float Ws[8][64];
    __shared__ __align__(16) float Xs[8][128];
    int tid = threadIdx.x;
    int tn = tid & 15, to = tid >> 4;
    int n0 = blockIdx.x * 128, o0 = blockIdx.y * 64;
    unsigned long long acc[4][4];
    #pragma unroll
    for (int i = 0; i < 4; i++)
        #pragma unroll
        for (int r = 0; r < 4; r++) acc[i][r] = 0ull;
    int wo = tid & 63, wck = tid >> 6;
    int xck = tid >> 5, xcol = (tid & 31) * 4;
    for (int c0 = 0; c0 < Cp; c0 += 8) {
        __syncthreads();
        int c = c0 + wck;
        Ws[wck][wo]     = (c < C)     ? W[(o0 + wo) * C + c]     : 0.f;
        Ws[wck + 4][wo] = (c + 4 < C) ? W[(o0 + wo) * C + c + 4] : 0.f;
        *(float4*)&Xs[xck][xcol] = *(const float4*)&X[(size_t)(c0 + xck) * NN + n0 + xcol];
        __syncthreads();
        #pragma unroll
        for (int ck = 0; ck < 8; ck++) {
            float4 wv = *(const float4*)&Ws[ck][to * 4];
            unsigned long long w0 = pk2(wv.x), w1 = pk2(wv.y), w2 = pk2(wv.z), w3 = pk2(wv.w);
            const unsigned long long* xr = (const unsigned long long*)&Xs[ck][0];
            unsigned long long x0 = xr[tn], x1 = xr[tn + 16], x2 = xr[tn + 32], x3 = xr[tn + 48];
            acc[0][0] = f2fma(w0, x0, acc[0][0]); acc[0][1] = f2fma(w0, x1, acc[0][1]);
            acc[0][2] = f2fma(w0, x2, acc[0][2]); acc[0][3] = f2fma(w0, x3, acc[0][3]);
            acc[1][0] = f2fma(w1, x0, acc[1][0]); acc[1][1] = f2fma(w1, x1, acc[1][1]);
            acc[1][2] = f2fma(w1, x2, acc[1][2]); acc[1][3] = f2fma(w1, x3, acc[1][3]);
            acc[2][0] = f2fma(w2, x0, acc[2][0]); acc[2][1] = f2fma(w2, x1, acc[2][1]);
            acc[2][2] = f2fma(w2, x2, acc[2][2]); acc[2][3] = f2fma(w2, x3, acc[2][3]);
            acc[3][0] = f2fma(w3, x0, acc[3][0]); acc[3][1] = f2fma(w3, x1, acc[3][1]);
            acc[3][2] = f2fma(w3, x2, acc[3][2]); acc[3][3] = f2fma(w3, x3, acc[3][3]);
        }
    }
    #pragma unroll
    for (int i = 0; i < 4; i++) {
        size_t row = (size_t)(o0 + to * 4 + i) * NN + n0 + 2 * tn;
        #pragma unroll
        for (int r = 0; r < 4; r++)
            *(unsigned long long*)&Y[row + 32 * r] = acc[i][r];
    }
}

// ---------------- per-channel sum / sumsq ----------------
__global__ void reduce_kernel(const float* __restrict__ Y, float2* __restrict__ stats) {
    int o = blockIdx.y;
    const float* y = Y + (size_t)o * NN + (size_t)blockIdx.x * 8192;
    float s = 0.f, s2 = 0.f;
    #pragma unroll
    for (int p = 0; p < 8; p++) {
        float4 v = *(const float4*)&y[p * 1024 + threadIdx.x * 4];
        s  += v.x + v.y + v.z + v.w;
        s2 += v.x * v.x + v.y * v.y + v.z * v.z + v.w * v.w;
    }
    #pragma unroll
    for (int off = 16; off; off >>= 1) {
        s  += __shfl_xor_sync(0xffffffffu, s, off);
        s2 += __shfl_xor_sync(0xffffffffu, s2, off);
    }
    __shared__ float ss[8], ss2[8];
    if ((threadIdx.x & 31) == 0) { ss[threadIdx.x >> 5] = s; ss2[threadIdx.x >> 5] = s2; }
    __syncthreads();
    if (threadIdx.x == 0) {
        float a = 0.f, b = 0.f;
        for (int w = 0; w < 8; w++) { a += ss[w]; b += ss2[w]; }
        atomicAdd(&stats[o].x, a);
        atomicAdd(&stats[o].y, b);
    }
}

// ---------------- BN + leaky-relu in place (feeds next conv) ----------------
__global__ void bn_apply(float* __restrict__ Y, const float2* __restrict__ stats,
                         const float* __restrict__ gg, const float* __restrict__ bb) {
    int o = blockIdx.y;
    float2 st = stats[o];
    float mu = st.x * (1.f / NN);
    float var = st.y * (1.f / NN) - mu * mu;
    float sc = rsqrtf(var + 1e-5f) * gg[o];
    float sh = bb[o] - mu * sc;
    int i = (blockIdx.x * blockDim.x + threadIdx.x) * 4;
    float4 v = *(float4*)&Y[(size_t)o * NN + i];
    float t;
    t = fmaf(v.x, sc, sh); v.x = t > 0.f ? t : NEG * t;
    t = fmaf(v.y, sc, sh); v.y = t > 0.f ? t : NEG * t;
    t = fmaf(v.z, sc, sh); v.z = t > 0.f ? t : NEG * t;
    t = fmaf(v.w, sc, sh); v.w = t > 0.f ? t : NEG * t;
    *(float4*)&Y[(size_t)o * NN + i] = v;
}

// ---------------- BN + leaky-relu + sigmoid-gate + max over K ----------------
__global__ void bnmax_kernel(const float* __restrict__ Y, const float2* __restrict__ stats,
                             const float* __restrict__ gg, const float* __restrict__ bb,
                             const float* __restrict__ gate, float* __restrict__ out,
                             int M, int K, int O) {
    int idx = blockIdx.x * blockDim.x + threadIdx.x;
    int o = idx / (B_ * M);
    int bm = idx - o * (B_ * M);
    if (o >= O) return;
    float2 st = stats[o];
    float mu = st.x * (1.f / NN);
    float var = st.y * (1.f / NN) - mu * mu;
    float sc = rsqrtf(var + 1e-5f) * gg[o];
    float sh = bb[o] - mu * sc;
    const float* y = Y + (size_t)o * NN + (size_t)bm * K;
    const float* gt = gate + (size_t)bm * K;
    float mx = -3.4e38f;
    for (int k = 0; k < K; k++) {
        float t = fmaf(y[k], sc, sh);
        t = t > 0.f ? t : NEG * t;
        mx = fmaxf(mx, gt[k] * t);
    }
    int b = bm / M, m = bm - b * M;
    out[((size_t)b * O + o) * M + m] = mx;
}

extern "C" void kernel_launch(void* const* d_in, const int* in_sizes, int n_in,
                              void* d_out, int out_size) {
    const float* xyz = (const float*)d_in[0];
    const float* w1a = (const float*)d_in[1];
    const float* g1a = (const float*)d_in[2];
    const float* b1a = (const float*)d_in[3];
    const float* w1b = (const float*)d_in[4];
    const float* g1b = (const float*)d_in[5];
    const float* b1b = (const float*)d_in[6];
    const float* w2a = (const float*)d_in[7];
    const float* g2a = (const float*)d_in[8];
    const float* b2a = (const float*)d_in[9];
    const float* w2b = (const float*)d_in[10];
    const float* g2b = (const float*)d_in[11];
    const float* b2b = (const float*)d_in[12];

    float *qs, *q1, *q2, *x, *gate, *ya, *yb, *f1;
    float2* stats;
    cudaGetSymbolAddress((void**)&qs, g_qs);
    cudaGetSymbolAddress((void**)&q1, g_q1);
    cudaGetSymbolAddress((void**)&q2, g_q2);
    cudaGetSymbolAddress((void**)&x,  g_x);
    cudaGetSymbolAddress((void**)&gate, g_gate);
    cudaGetSymbolAddress((void**)&ya, g_ya);
    cudaGetSymbolAddress((void**)&yb, g_yb);
    cudaGetSymbolAddress((void**)&f1, g_f1);
    cudaGetSymbolAddress((void**)&stats, g_stats);

    const float r2a = (float)(0.15 * 0.15);
    const float r2b = (float)(0.3 * 0.3);

    // ---------- stage 1 ----------
    shift_kernel<<<(B_ * 512 + 255) / 256, 256>>>(xyz, qs, 512);
    fps_kernel<<<B_, 512>>>(qs, q1, 512, 256);
    group_kernel<<<1024, 256>>>(q1, 256, xyz, 512, (const float*)0, 0, 1,
                                r2a, 0.15f, 16, x, gate);
    gemm_kernel<<<dim3(NN / 128, 1), 256>>>(w1a, x, ya, 6, 8);
    cudaMemsetAsync(stats, 0, 64 * sizeof(float2), 0);
    reduce_kernel<<<dim3(16, 64), 256>>>(ya, stats);
    bn_apply<<<dim3(NN / 1024, 64), 256>>>(ya, stats, g1a, b1a);
    gemm_kernel<<<dim3(NN / 128, 2), 256>>>(w1b, ya, yb, 64, 64);
    cudaMemsetAsync(stats, 0, 128 * sizeof(float2), 0);
    reduce_kernel<<<dim3(16, 128), 256>>>(yb, stats);
    bnmax_kernel<<<(128 * B_ * 256) / 256, 256>>>(yb, stats, g1b, b1b, gate, f1,
                                                  256, 16, 128);

    // ---------- stage 2 ----------
    shift_kernel<<<(B_ * 256 + 255) / 256, 256>>>(q1, qs, 256);
    fps_kernel<<<B_, 256>>>(qs, q2, 256, 128);
    group_kernel<<<512, 256>>>(q2, 128, q1, 256, f1, 128, 0,
                               r2b, 0.3f, 32, x, gate);
    gemm_kernel<<<dim3(NN / 128, 2), 256>>>(w2a, x, ya, 131, 136);
    cudaMemsetAsync(stats, 0, 128 * sizeof(float2), 0);
    reduce_kernel<<<dim3(16, 128), 256>>>(ya, stats);
    bn_apply<<<dim3(NN / 1024, 128), 256>>>(ya, stats, g2a, b2a);
    gemm_kernel<<<dim3(NN / 128, 4), 256>>>(w2b, ya, yb, 128, 128);
    cudaMemsetAsync(stats, 0, 256 * sizeof(float2), 0);
    reduce_kernel<<<dim3(16, 256), 256>>>(yb, stats);
    bnmax_kernel<<<(256 * B_ * 128) / 256, 256>>>(yb, stats, g2b, b2b, gate,
                                                  (float*)d_out, 128, 32, 256);
}

// round 4
// speedup vs baseline: 1.2445x; 1.2445x over previous
#include <cuda_runtime.h>
#include <math.h>

#define B_ 32
#define NN 131072
#define NEG 0.2f

typedef unsigned long long ull;

// ---------------- scratch (device globals; zero-initialized) ----------------
__device__ __align__(16) float g_qs[B_ * 512 * 3];
__device__ __align__(16) float g_q1[B_ * 256 * 3];
__device__ __align__(16) float g_q2[B_ * 128 * 3];
__device__ __align__(16) float g_x[136 * NN];
__device__ __align__(16) float g_gate[NN];
__device__ __align__(16) float g_ya[128 * NN];
__device__ __align__(16) float g_yb[256 * NN];
__device__ __align__(16) float g_f1[B_ * 128 * 256];
__device__ float2 g_stats4[4 * 256];   // 4 layer stat buffers

// ---------------- packed f32x2 helpers ----------------
__device__ __forceinline__ ull pk2(float a) {
    ull r; asm("mov.b64 %0, {%1, %1};" : "=l"(r) : "f"(a)); return r;
}
__device__ __forceinline__ ull f2fma(ull a, ull b, ull c) {
    ull d; asm("fma.rn.f32x2 %0, %1, %2, %3;" : "=l"(d) : "l"(a), "l"(b), "l"(c));
    return d;
}
__device__ __forceinline__ void unpk(ull v, float& lo, float& hi) {
    asm("mov.b64 {%0, %1}, %2;" : "=f"(lo), "=f"(hi) : "l"(v));
}
__device__ __forceinline__ unsigned smem_u32(const void* p) {
    unsigned a;
    asm("{ .reg .u64 t; cvta.to.shared.u64 t, %1; cvt.u32.u64 %0, t; }" : "=r"(a) : "l"(p));
    return a;
}

// ---------------- shift_point ----------------
__global__ void shift_kernel(const float* __restrict__ xyz, float* __restrict__ q, int N) {
    int i = blockIdx.x * blockDim.x + threadIdx.x;
    if (i >= B_ * N) return;
    int b = i / N, n = i - b * N;
    if ((b & 15) < 15) {
        const float* s = xyz + ((size_t)(b + 1) * N + n) * 3;
        float* d = q + (size_t)i * 3;
        d[0] = s[0]; d[1] = s[1]; d[2] = s[2];
    } else {
        int b0 = b - 15;
        #pragma unroll
        for (int c = 0; c < 3; c++) {
            float s = 0.f;
            for (int t = 0; t < 15; t++)
                s = __fadd_rn(s, __fsub_rn(xyz[((size_t)(b0 + t + 1) * N + n) * 3 + c],
                                           xyz[((size_t)(b0 + t) * N + n) * 3 + c]));
            q[(size_t)i * 3 + c] = __fadd_rn(xyz[((size_t)b * N + n) * 3 + c],
                                             __fdiv_rn(s, 15.f));
        }
    }
}

// ---------------- FPS: 128 threads, PPT points per thread ----------------
template <int PPT>
__global__ void fps_kernel(const float* __restrict__ q, float* __restrict__ qsel,
                           int NP) {
    const int N = PPT * 128;
    __shared__ float sx[512], sy[512], sz[512];
    __shared__ ull wk[4];
    int b = blockIdx.x, tid = threadIdx.x, w = tid >> 5;
    const float* qb = q + (size_t)b * N * 3;
    float px[PPT], py[PPT], pz[PPT], mind[PPT];
    #pragma unroll
    for (int p = 0; p < PPT; p++) {
        int j = tid + 128 * p;
        px[p] = qb[j * 3 + 0]; py[p] = qb[j * 3 + 1]; pz[p] = qb[j * 3 + 2];
        sx[j] = px[p]; sy[j] = py[p]; sz[j] = pz[p];
        mind[p] = 1e10f;
    }
    __syncthreads();
    float lx = sx[0], ly = sy[0], lz = sz[0];
    if (tid == 0) {
        float* d = qsel + (size_t)b * NP * 3;
        d[0] = lx; d[1] = ly; d[2] = lz;
    }
    for (int t = 1; t < NP; t++) {
        ull key = 0;
        #pragma unroll
        for (int p = 0; p < PPT; p++) {
            float dx = __fsub_rn(px[p], lx), dy = __fsub_rn(py[p], ly), dz = __fsub_rn(pz[p], lz);
            float d = __fadd_rn(__fadd_rn(__fmul_rn(dx, dx), __fmul_rn(dy, dy)),
                                __fmul_rn(dz, dz));
            mind[p] = fminf(mind[p], d);
            ull k = (((ull)__float_as_uint(mind[p])) << 32) | (unsigned)(N - 1 - (tid + 128 * p));
            if (k > key) key = k;
        }
        #pragma unroll
        for (int off = 16; off; off >>= 1) {
            ull o = __shfl_xor_sync(0xffffffffu, key, off);
            if (o > key) key = o;
        }
        if ((tid & 31) == 0) wk[w] = key;
        __syncthreads();
        ull best = wk[0];
        #pragma unroll
        for (int i = 1; i < 4; i++) { ull o = wk[i]; if (o > best) best = o; }
        int bi = N - 1 - (int)(best & 0xffffffffu);
        lx = sx[bi]; ly = sy[bi]; lz = sz[bi];
        if (tid == 0) {
            float* d2 = qsel + ((size_t)b * NP + t) * 3;
            d2[0] = lx; d2[1] = ly; d2[2] = lz;
        }
        __syncthreads();
    }
}

// ---------------- ball query + build GEMM input + gate (one warp/query) -------
__global__ void group_kernel(const float* __restrict__ q, int M,
                             const float* __restrict__ sup, int N,
                             const float* __restrict__ feats, int C, int feat_xyz,
                             float r2, float radius, int K,
                             float* __restrict__ x, float* __restrict__ gate) {
    int gw = (blockIdx.x * blockDim.x + threadIdx.x) >> 5;
    int lane = threadIdx.x & 31;
    int wl = threadIdx.x >> 5;
    __shared__ int slist[8][32];
    if (gw >= B_ * M) return;
    int b = gw / M, m = gw - b * M;
    const float* qp = q + ((size_t)b * M + m) * 3;
    float qx = qp[0], qy = qp[1], qz = qp[2];
    const float* xb = sup + (size_t)b * N * 3;
    int count = 0;
    for (int base = 0; base < N; base += 32) {
        int j = base + lane;
        float dx = __fsub_rn(qx, xb[j * 3 + 0]);
        float dy = __fsub_rn(qy, xb[j * 3 + 1]);
        float dz = __fsub_rn(qz, xb[j * 3 + 2]);
        float d2 = __fadd_rn(__fadd_rn(__fmul_rn(dx, dx), __fmul_rn(dy, dy)),
                             __fmul_rn(dz, dz));
        bool in = d2 < r2;
        unsigned bal = __ballot_sync(0xffffffffu, in);
        int pos = count + __popc(bal & ((1u << lane) - 1u));
        if (in && pos < K) slist[wl][pos] = j;
        count += __popc(bal);
        if (count >= K) break;
    }
    if (count > K) count = K;
    __syncwarp();
    int pad = (count > 0) ? slist[wl][0] : 0;
    if (lane < K && lane >= count) slist[wl][lane] = pad;
    __syncwarp();
    int nb = (b * M + m) * K;
    if (lane < K) {
        int j = slist[wl][lane];
        float gx = xb[j * 3 + 0], gy = xb[j * 3 + 1], gz = xb[j * 3 + 2];
        float dpx = (gx - qx) / radius, dpy = (gy - qy) / radius, dpz = (gz - qz) / radius;
        x[0 * NN + nb + lane] = dpx;
        x[1 * NN + nb + lane] = dpy;
        x[2 * NN + nb + lane] = dpz;
        float dist = sqrtf(dpx * dpx + dpy * dpy + dpz * dpz);
        gate[nb + lane] = 1.0f / (1.0f + expf(-dist));
        if (feat_xyz) {
            x[3 * NN + nb + lane] = gx;
            x[4 * NN + nb + lane] = gy;
            x[5 * NN + nb + lane] = gz;
        } else {
            for (int c = 0; c < C; c++)
                x[(size_t)(3 + c) * NN + nb + lane] = feats[((size_t)b * C + c) * N + j];
        }
    }
}

// ---------------- GEMM v2: 64(o) x 256(n) tile, cp.async pipeline,
//                  fused per-channel sum/sumsq epilogue ----------------
// smem: Ws[136][64] floats @0, Xs[2][8][256] floats @34816
#define WS_FLOATS (136 * 64)
#define XS_OFF    WS_FLOATS
#define GEMM_SMEM ((WS_FLOATS + 2 * 8 * 256) * 4)

__global__ void __launch_bounds__(256, 2) gemm_kernel(
    const float* __restrict__ W, const float* __restrict__ X,
    float* __restrict__ Y, int C, int Cp, float2* __restrict__ stats) {
    extern __shared__ float sm[];
    float* Ws = sm;
    float* Xs = sm + XS_OFF;
    int tid = threadIdx.x;
    int lane = tid & 31;
    int to = tid >> 4, tn = tid & 15;
    int o0 = blockIdx.x * 64;
    int n0 = blockIdx.y * 256;

    // preload all of W (zero-padded) into smem
    for (int idx = tid; idx < Cp * 64; idx += 256) {
        int c = idx >> 6, wo = idx & 63;
        Ws[idx] = (c < C) ? W[(o0 + wo) * C + c] : 0.f;
    }

    // cp.async staging: 2 chunks (16B) per thread per tile
    unsigned xs_addr = smem_u32(Xs);
    int q0 = tid * 2;
    int row0 = q0 >> 6, col0 = (q0 & 63) * 4;
    int row1 = (q0 + 1) >> 6, col1 = ((q0 + 1) & 63) * 4;

    int niter = Cp >> 3;
    // prologue: stage tile 0 into buf 0
    {
        const float* s0 = X + (size_t)row0 * NN + n0 + col0;
        const float* s1 = X + (size_t)row1 * NN + n0 + col1;
        asm volatile("cp.async.ca.shared.global [%0], [%1], 16;"
                     :: "r"(xs_addr + (row0 * 256 + col0) * 4), "l"(s0));
        asm volatile("cp.async.ca.shared.global [%0], [%1], 16;"
                     :: "r"(xs_addr + (row1 * 256 + col1) * 4), "l"(s1));
        asm volatile("cp.async.commit_group;");
    }

    ull acc[4][4][2];
    #pragma unroll
    for (int i = 0; i < 4; i++)
        #pragma unroll
        for (int r = 0; r < 4; r++) { acc[i][r][0] = 0ull; acc[i][r][1] = 0ull; }

    __syncthreads();   // Ws ready

    for (int it = 0; it < niter; it++) {
        int buf = it & 1;
        asm volatile("cp.async.wait_group 0;");
        __syncthreads();
        if (it + 1 < niter) {
            int c0n = (it + 1) * 8;
            int nbuf = buf ^ 1;
            const float* s0 = X + (size_t)(c0n + row0) * NN + n0 + col0;
            const float* s1 = X + (size_t)(c0n + row1) * NN + n0 + col1;
            asm volatile("cp.async.ca.shared.global [%0], [%1], 16;"
                         :: "r"(xs_addr + (nbuf * 2048 + row0 * 256 + col0) * 4), "l"(s0));
            asm volatile("cp.async.ca.shared.global [%0], [%1], 16;"
                         :: "r"(xs_addr + (nbuf * 2048 + row1 * 256 + col1) * 4), "l"(s1));
            asm volatile("cp.async.commit_group;");
        }
        int c0 = it * 8;
        #pragma unroll
        for (int ck = 0; ck < 8; ck++) {
            float4 wv = *(const float4*)&Ws[(c0 + ck) * 64 + to * 4];
            ull w0 = pk2(wv.x), w1 = pk2(wv.y), w2 = pk2(wv.z), w3 = pk2(wv.w);
            const ulonglong2* xr =
                (const ulonglong2*)&Xs[buf * 2048 + ck * 256];
            #pragma unroll
            for (int r = 0; r < 4; r++) {
                ulonglong2 xv = xr[tn + 16 * r];
                acc[0][r][0] = f2fma(w0, xv.x, acc[0][r][0]);
                acc[0][r][1] = f2fma(w0, xv.y, acc[0][r][1]);
                acc[1][r][0] = f2fma(w1, xv.x, acc[1][r][0]);
                acc[1][r][1] = f2fma(w1, xv.y, acc[1][r][1]);
                acc[2][r][0] = f2fma(w2, xv.x, acc[2][r][0]);
                acc[2][r][1] = f2fma(w2, xv.y, acc[2][r][1]);
                acc[3][r][0] = f2fma(w3, xv.x, acc[3][r][0]);
                acc[3][r][1] = f2fma(w3, xv.y, acc[3][r][1]);
            }
        }
    }

    // epilogue: store + fused per-channel sum/sumsq
    #pragma unroll
    for (int i = 0; i < 4; i++) {
        int o = o0 + to * 4 + i;
        float s = 0.f, s2 = 0.f;
        size_t rowp = (size_t)o * NN + n0 + 4 * tn;
        #pragma unroll
        for (int r = 0; r < 4; r++) {
            float a, bq, c, d;
            unpk(acc[i][r][0], a, bq);
            unpk(acc[i][r][1], c, d);
            s += (a + bq) + (c + d);
            s2 += (a * a + bq * bq) + (c * c + d * d);
            ulonglong2 st; st.x = acc[i][r][0]; st.y = acc[i][r][1];
            *(ulonglong2*)&Y[rowp + 64 * r] = st;
        }
        #pragma unroll
        for (int off = 8; off; off >>= 1) {
            s  += __shfl_xor_sync(0xffffffffu, s, off);
            s2 += __shfl_xor_sync(0xffffffffu, s2, off);
        }
        if ((lane & 15) == 0) {
            atomicAdd(&stats[o].x, s);
            atomicAdd(&stats[o].y, s2);
        }
    }
}

// ---------------- BN + leaky-relu in place ----------------
__global__ void bn_apply(float* __restrict__ Y, const float2* __restrict__ stats,
                         const float* __restrict__ gg, const float* __restrict__ bb) {
    int o = blockIdx.y;
    float2 st = stats[o];
    float mu = st.x * (1.f / NN);
    float var = st.y * (1.f / NN) - mu * mu;
    float sc = rsqrtf(var + 1e-5f) * gg[o];
    float sh = bb[o] - mu * sc;
    int i = (blockIdx.x * blockDim.x + threadIdx.x) * 4;
    float4 v = *(float4*)&Y[(size_t)o * NN + i];
    float t;
    t = fmaf(v.x, sc, sh); v.x = t > 0.f ? t : NEG * t;
    t = fmaf(v.y, sc, sh); v.y = t > 0.f ? t : NEG * t;
    t = fmaf(v.z, sc, sh); v.z = t > 0.f ? t : NEG * t;
    t = fmaf(v.w, sc, sh); v.w = t > 0.f ? t : NEG * t;
    *(float4*)&Y[(size_t)o * NN + i] = v;
}

// ---------------- BN + leaky-relu + gate + max over K ----------------
__global__ void bnmax_kernel(const float* __restrict__ Y, const float2* __restrict__ stats,
                             const float* __restrict__ gg, const float* __restrict__ bb,
                             const float* __restrict__ gate, float* __restrict__ out,
                             int M, int K, int O) {
    int idx = blockIdx.x * blockDim.x + threadIdx.x;
    int o = idx / (B_ * M);
    int bm = idx - o * (B_ * M);
    if (o >= O) return;
    float2 st = stats[o];
    float mu = st.x * (1.f / NN);
    float var = st.y * (1.f / NN) - mu * mu;
    float sc = rsqrtf(var + 1e-5f) * gg[o];
    float sh = bb[o] - mu * sc;
    const float* y = Y + (size_t)o * NN + (size_t)bm * K;
    const float* gt = gate + (size_t)bm * K;
    float mx = -3.4e38f;
    for (int k = 0; k < K; k++) {
        float t = fmaf(y[k], sc, sh);
        t = t > 0.f ? t : NEG * t;
        mx = fmaxf(mx, gt[k] * t);
    }
    int b = bm / M, m = bm - b * M;
    out[((size_t)b * O + o) * M + m] = mx;
}

extern "C" void kernel_launch(void* const* d_in, const int* in_sizes, int n_in,
                              void* d_out, int out_size) {
    const float* xyz = (const float*)d_in[0];
    const float* w1a = (const float*)d_in[1];
    const float* g1a = (const float*)d_in[2];
    const float* b1a = (const float*)d_in[3];
    const float* w1b = (const float*)d_in[4];
    const float* g1b = (const float*)d_in[5];
    const float* b1b = (const float*)d_in[6];
    const float* w2a = (const float*)d_in[7];
    const float* g2a = (const float*)d_in[8];
    const float* b2a = (const float*)d_in[9];
    const float* w2b = (const float*)d_in[10];
    const float* g2b = (const float*)d_in[11];
    const float* b2b = (const float*)d_in[12];

    float *qs, *q1, *q2, *x, *gate, *ya, *yb, *f1;
    float2* st;
    cudaGetSymbolAddress((void**)&qs, g_qs);
    cudaGetSymbolAddress((void**)&q1, g_q1);
    cudaGetSymbolAddress((void**)&q2, g_q2);
    cudaGetSymbolAddress((void**)&x,  g_x);
    cudaGetSymbolAddress((void**)&gate, g_gate);
    cudaGetSymbolAddress((void**)&ya, g_ya);
    cudaGetSymbolAddress((void**)&yb, g_yb);
    cudaGetSymbolAddress((void**)&f1, g_f1);
    cudaGetSymbolAddress((void**)&st, g_stats4);
    float2* st1a = st, *st1b = st + 256, *st2a = st + 512, *st2b = st + 768;

    cudaFuncSetAttribute(gemm_kernel, cudaFuncAttributeMaxDynamicSharedMemorySize,
                         GEMM_SMEM);

    const float r2a = (float)(0.15 * 0.15);
    const float r2b = (float)(0.3 * 0.3);

    cudaMemsetAsync(st, 0, 4 * 256 * sizeof(float2), 0);

    // ---------- stage 1 ----------
    shift_kernel<<<(B_ * 512 + 255) / 256, 256>>>(xyz, qs, 512);
    fps_kernel<4><<<B_, 128>>>(qs, q1, 256);
    group_kernel<<<1024, 256>>>(q1, 256, xyz, 512, (const float*)0, 0, 1,
                                r2a, 0.15f, 16, x, gate);
    gemm_kernel<<<dim3(1, NN / 256), 256, GEMM_SMEM>>>(w1a, x, ya, 6, 8, st1a);
    bn_apply<<<dim3(NN / 1024, 64), 256>>>(ya, st1a, g1a, b1a);
    gemm_kernel<<<dim3(2, NN / 256), 256, GEMM_SMEM>>>(w1b, ya, yb, 64, 64, st1b);
    bnmax_kernel<<<(128 * B_ * 256) / 256, 256>>>(yb, st1b, g1b, b1b, gate, f1,
                                                  256, 16, 128);

    // ---------- stage 2 ----------
    shift_kernel<<<(B_ * 256 + 255) / 256, 256>>>(q1, qs, 256);
    fps_kernel<2><<<B_, 128>>>(qs, q2, 128);
    group_kernel<<<512, 256>>>(q2, 128, q1, 256, f1, 128, 0,
                               r2b, 0.3f, 32, x, gate);
    gemm_kernel<<<dim3(2, NN / 256), 256, GEMM_SMEM>>>(w2a, x, ya, 131, 136, st2a);
    bn_apply<<<dim3(NN / 1024, 128), 256>>>(ya, st2a, g2a, b2a);
    gemm_kernel<<<dim3(4, NN / 256), 256, GEMM_SMEM>>>(w2b, ya, yb, 128, 128, st2b);
    bnmax_kernel<<<(256 * B_ * 128) / 256, 256>>>(yb, st2b, g2b, b2b, gate,
                                                  (float*)d_out, 128, 32, 256);
}